// round 1
// baseline (speedup 1.0000x reference)
#include <cuda_runtime.h>
#include <cuda_bf16.h>
#include <cstdint>

// ---------------------------------------------------------------------------
// Problem constants (fixed by the reference)
// ---------------------------------------------------------------------------
#define N_NODES  50000
#define N_EDGES  800000
#define NODE_IN  128
#define EDGE_OUT 64
#define DIN      320      // NODE_IN + 3*EDGE_OUT
#define HID      512
#define NODE_OUT 128
#define CAP      96       // bucket capacity per node (max degree ~45 whp)

// ---------------------------------------------------------------------------
// Static device scratch (allocation-free rule: __device__ globals only)
// ---------------------------------------------------------------------------
__device__ int   d_flag;                       // 1 => edge_index is int32
__device__ int   d_cursor[N_NODES];            // per-node edge count / cursor
__device__ int   d_bucket[N_NODES * CAP];      // edge ids per node
__device__ float d_H[N_NODES * DIN];           // concatenated features [50000,320]
__device__ float d_Hmid[N_NODES * HID];        // hidden activations   [50000,512]

// ---------------------------------------------------------------------------
// K0: reset cursors + dtype flag
// ---------------------------------------------------------------------------
__global__ void k_init() {
    int i = blockIdx.x * blockDim.x + threadIdx.x;
    if (i < N_NODES) d_cursor[i] = 0;
    if (i == 0) d_flag = 0;
}

// ---------------------------------------------------------------------------
// K1: probe edge_index dtype. If data is int32, reading it as int64 packs two
// node indices per word -> value >= 2^32 with overwhelming probability.
// ---------------------------------------------------------------------------
__global__ void k_probe(const void* __restrict__ ei) {
    const long long v = ((const long long*)ei)[threadIdx.x];   // 256 samples
    if (v < 0 || v >= (long long)N_NODES) d_flag = 1;          // racy same-value store: fine
}

// ---------------------------------------------------------------------------
// K2: bucket edges by destination node (edge_index row 1 = col)
// ---------------------------------------------------------------------------
__global__ void k_bucket(const void* __restrict__ ei) {
    int e = blockIdx.x * blockDim.x + threadIdx.x;
    if (e >= N_EDGES) return;
    int c;
    if (d_flag) {
        c = ((const int*)ei)[N_EDGES + e];
    } else {
        c = (int)((const long long*)ei)[N_EDGES + e];
    }
    int pos = atomicAdd(&d_cursor[c], 1);
    if (pos < CAP) d_bucket[c * CAP + pos] = e;
}

// ---------------------------------------------------------------------------
// K3: per-node segmented reduce (sum / max / mean) + build concatenated H row
// 64 threads per node, one feature each; 4-way unrolled accumulators for MLP.
// ---------------------------------------------------------------------------
__global__ void __launch_bounds__(64) k_buildH(const float* __restrict__ x,
                                               const float* __restrict__ edge_attr) {
    __shared__ int se[CAP];
    const int n = blockIdx.x;
    const int f = threadIdx.x;                 // 0..63

    const int total = d_cursor[n];
    const int ec = total < CAP ? total : CAP;

    for (int i = f; i < ec; i += 64) se[i] = d_bucket[n * CAP + i];
    __syncthreads();

    const float NEG_INF = __int_as_float(0xff800000u);
    float s0 = 0.f, s1 = 0.f, s2 = 0.f, s3 = 0.f;
    float m0 = NEG_INF, m1 = NEG_INF, m2 = NEG_INF, m3 = NEG_INF;

    int i = 0;
    for (; i + 4 <= ec; i += 4) {
        float v0 = __ldg(&edge_attr[(size_t)se[i + 0] * EDGE_OUT + f]);
        float v1 = __ldg(&edge_attr[(size_t)se[i + 1] * EDGE_OUT + f]);
        float v2 = __ldg(&edge_attr[(size_t)se[i + 2] * EDGE_OUT + f]);
        float v3 = __ldg(&edge_attr[(size_t)se[i + 3] * EDGE_OUT + f]);
        s0 += v0; s1 += v1; s2 += v2; s3 += v3;
        m0 = fmaxf(m0, v0); m1 = fmaxf(m1, v1);
        m2 = fmaxf(m2, v2); m3 = fmaxf(m3, v3);
    }
    for (; i < ec; i++) {
        float v = __ldg(&edge_attr[(size_t)se[i] * EDGE_OUT + f]);
        s0 += v; m0 = fmaxf(m0, v);
    }
    const float sum = (s0 + s1) + (s2 + s3);
    float mx = fmaxf(fmaxf(m0, m1), fmaxf(m2, m3));
    if (ec == 0) mx = 0.f;                     // reference: empty segment max -> 0

    float* Hrow = d_H + (size_t)n * DIN;
    Hrow[f]            = x[(size_t)n * NODE_IN + f];
    Hrow[64 + f]       = x[(size_t)n * NODE_IN + 64 + f];
    Hrow[NODE_IN + f]  = sum;                                  // s_sum  @128
    Hrow[192 + f]      = mx;                                   // s_max  @192
    Hrow[256 + f]      = sum / fmaxf((float)total, 1.f);       // s_mean @256
}

// ---------------------------------------------------------------------------
// K4/K5: tiled fp32 SGEMM, C = act(A @ B + bias)
// A row-major [M,K], B row-major [K,N], C row-major [M,N]
// 128x128 block tile, BK=8, 8x8 per-thread microtile, 256 threads.
// ---------------------------------------------------------------------------
#define BM 128
#define BN 128
#define BK 8
#define TM 8
#define TN 8

__global__ void __launch_bounds__(256, 2)
k_sgemm(const float* __restrict__ A, const float* __restrict__ B,
        const float* __restrict__ bias, float* __restrict__ C,
        int M, int N, int K, int relu) {
    __shared__ float As[BK][BM + 4];   // transposed A tile, padded vs STS conflicts
    __shared__ float Bs[BK][BN];

    const int col0 = blockIdx.x * BN;
    const int row0 = blockIdx.y * BM;
    const int tid  = threadIdx.x;

    const int trow = (tid / 16) * TM;
    const int tcol = (tid % 16) * TN;

    // load mappings
    const int aRow = tid >> 1;          // 0..127
    const int aCol = (tid & 1) * 4;     // 0 or 4
    const int bRow = tid >> 5;          // 0..7
    const int bCol = (tid & 31) * 4;    // 0..124

    float acc[TM][TN];
#pragma unroll
    for (int ii = 0; ii < TM; ii++)
#pragma unroll
        for (int jj = 0; jj < TN; jj++) acc[ii][jj] = 0.f;

    for (int k0 = 0; k0 < K; k0 += BK) {
        // --- A tile (guard M edge) ---
        float4 av = make_float4(0.f, 0.f, 0.f, 0.f);
        const int gr = row0 + aRow;
        if (gr < M) av = *(const float4*)(A + (size_t)gr * K + k0 + aCol);
        As[aCol + 0][aRow] = av.x;
        As[aCol + 1][aRow] = av.y;
        As[aCol + 2][aRow] = av.z;
        As[aCol + 3][aRow] = av.w;
        // --- B tile ---
        float4 bv = *(const float4*)(B + (size_t)(k0 + bRow) * N + col0 + bCol);
        *(float4*)&Bs[bRow][bCol] = bv;
        __syncthreads();

#pragma unroll
        for (int k = 0; k < BK; k++) {
            float areg[TM], breg[TN];
            *(float4*)&areg[0] = *(const float4*)&As[k][trow];
            *(float4*)&areg[4] = *(const float4*)&As[k][trow + 4];
            *(float4*)&breg[0] = *(const float4*)&Bs[k][tcol];
            *(float4*)&breg[4] = *(const float4*)&Bs[k][tcol + 4];
#pragma unroll
            for (int ii = 0; ii < TM; ii++)
#pragma unroll
                for (int jj = 0; jj < TN; jj++)
                    acc[ii][jj] += areg[ii] * breg[jj];
        }
        __syncthreads();
    }

    // epilogue: bias + optional relu
    float bb[TN];
#pragma unroll
    for (int jj = 0; jj < TN; jj++) bb[jj] = bias[col0 + tcol + jj];

#pragma unroll
    for (int ii = 0; ii < TM; ii++) {
        const int gr = row0 + trow + ii;
        if (gr >= M) continue;
        float4 v0, v1;
        v0.x = acc[ii][0] + bb[0]; v0.y = acc[ii][1] + bb[1];
        v0.z = acc[ii][2] + bb[2]; v0.w = acc[ii][3] + bb[3];
        v1.x = acc[ii][4] + bb[4]; v1.y = acc[ii][5] + bb[5];
        v1.z = acc[ii][6] + bb[6]; v1.w = acc[ii][7] + bb[7];
        if (relu) {
            v0.x = fmaxf(v0.x, 0.f); v0.y = fmaxf(v0.y, 0.f);
            v0.z = fmaxf(v0.z, 0.f); v0.w = fmaxf(v0.w, 0.f);
            v1.x = fmaxf(v1.x, 0.f); v1.y = fmaxf(v1.y, 0.f);
            v1.z = fmaxf(v1.z, 0.f); v1.w = fmaxf(v1.w, 0.f);
        }
        float* cp = C + (size_t)gr * N + col0 + tcol;
        *(float4*)(cp)     = v0;
        *(float4*)(cp + 4) = v1;
    }
}

// ---------------------------------------------------------------------------
// Host launcher (graph-capturable: kernel launches only)
// ---------------------------------------------------------------------------
extern "C" void kernel_launch(void* const* d_in, const int* in_sizes, int n_in,
                              void* d_out, int out_size) {
    const float* x         = (const float*)d_in[0];
    const void*  ei        = d_in[1];                 // int64 or int32 (probed)
    const float* edge_attr = (const float*)d_in[2];
    // d_in[3] = u (unused), d_in[4] = batch (unused)
    const float* W1 = (const float*)d_in[5];
    const float* b1 = (const float*)d_in[6];
    const float* W2 = (const float*)d_in[7];
    const float* b2 = (const float*)d_in[8];
    float* out = (float*)d_out;

    void *pH = nullptr, *pHmid = nullptr;
    cudaGetSymbolAddress(&pH, d_H);
    cudaGetSymbolAddress(&pHmid, d_Hmid);
    float* H    = (float*)pH;
    float* Hmid = (float*)pHmid;

    // 0) reset
    k_init<<<(N_NODES + 255) / 256, 256>>>();
    // 1) dtype probe
    k_probe<<<1, 256>>>(ei);
    // 2) bucket edges by destination node
    k_bucket<<<(N_EDGES + 255) / 256, 256>>>(ei);
    // 3) segmented reduce + build H = [x | sum | max | mean]
    k_buildH<<<N_NODES, 64>>>(x, edge_attr);
    // 4) Hmid = relu(H @ W1 + b1)   [50000,320]x[320,512]
    {
        dim3 grid(HID / BN, (N_NODES + BM - 1) / BM);
        k_sgemm<<<grid, 256>>>(H, W1, b1, Hmid, N_NODES, HID, DIN, 1);
    }
    // 5) out = Hmid @ W2 + b2       [50000,512]x[512,128]
    {
        dim3 grid(NODE_OUT / BN, (N_NODES + BM - 1) / BM);
        k_sgemm<<<grid, 256>>>(Hmid, W2, b2, out, N_NODES, NODE_OUT, HID, 0);
    }
}

// round 3
// speedup vs baseline: 1.7896x; 1.7896x over previous
#include <cuda_runtime.h>
#include <cuda_bf16.h>
#include <cstdint>

// ---------------------------------------------------------------------------
// Problem constants
// ---------------------------------------------------------------------------
#define N_NODES  50000
#define N_EDGES  800000
#define NODE_IN  128
#define EDGE_OUT 64
#define DIN      320
#define HID      512
#define NODE_OUT 128
#define CAP      96
#define MPAD     50048          // 391 * 128
#define K1P      (DIN * 3)      // 960  (triple-expanded K for GEMM1)
#define K2P      (HID * 3)      // 1536 (triple-expanded K for GEMM2)

// ---------------------------------------------------------------------------
// Static device scratch (__device__ globals only; no allocations)
// ---------------------------------------------------------------------------
__device__ int d_flag;
__device__ int d_cursor[N_NODES];
__device__ int d_bucket[N_NODES * CAP];
__device__ __align__(16) unsigned short d_A1[(size_t)MPAD * K1P];     // A' for GEMM1
__device__ __align__(16) unsigned short d_Hm[(size_t)MPAD * K2P];     // A' for GEMM2
__device__ __align__(16) unsigned short d_W1p[HID * K1P];             // B' (W1^T triple)
__device__ __align__(16) unsigned short d_W2p[NODE_OUT * K2P];        // B' (W2^T triple)

// ---------------------------------------------------------------------------
// Helpers
// ---------------------------------------------------------------------------
__device__ __forceinline__ uint32_t smem_u32_(const void* p) {
    uint32_t a;
    asm("{ .reg .u64 t; cvta.to.shared.u64 t, %1; cvt.u32.u64 %0, t; }" : "=r"(a) : "l"(p));
    return a;
}

// bf16 hi/lo split: v ~= hi + lo, |err| <= 2^-17 |v|
__device__ __forceinline__ void split_u16(float v, unsigned short& h, unsigned short& l) {
    __nv_bfloat16 hb = __float2bfloat16(v);
    __nv_bfloat16 lb = __float2bfloat16(v - __bfloat162float(hb));
    h = __bfloat16_as_ushort(hb);
    l = __bfloat16_as_ushort(lb);
}

__device__ __forceinline__ void cpa16(uint32_t s, const void* g) {
    asm volatile("cp.async.cg.shared.global [%0], [%1], 16;"
                 :: "r"(s), "l"(__cvta_generic_to_global(g)));
}
#define CP_COMMIT() asm volatile("cp.async.commit_group;")
#define CP_WAIT1()  asm volatile("cp.async.wait_group 1;")

#define LDSM4(r, a)                                                          \
    asm volatile("ldmatrix.sync.aligned.m8n8.x4.shared.b16 {%0,%1,%2,%3}, [%4];" \
        : "=r"((r)[0]), "=r"((r)[1]), "=r"((r)[2]), "=r"((r)[3]) : "r"(a))

__device__ __forceinline__ void mma16816(float* c, const uint32_t* a, const uint32_t* b) {
    asm volatile(
        "mma.sync.aligned.m16n8k16.row.col.f32.bf16.bf16.f32 "
        "{%0,%1,%2,%3}, {%4,%5,%6,%7}, {%8,%9}, {%0,%1,%2,%3};"
        : "+f"(c[0]), "+f"(c[1]), "+f"(c[2]), "+f"(c[3])
        : "r"(a[0]), "r"(a[1]), "r"(a[2]), "r"(a[3]), "r"(b[0]), "r"(b[1]));
}

// ---------------------------------------------------------------------------
// K0: init cursors + flag
// ---------------------------------------------------------------------------
__global__ void k_init() {
    int i = blockIdx.x * blockDim.x + threadIdx.x;
    if (i < N_NODES) d_cursor[i] = 0;
    if (i == 0) d_flag = 0;
}

// K1: dtype probe (int64 vs int32 edge_index)
__global__ void k_probe(const void* __restrict__ ei) {
    const long long v = ((const long long*)ei)[threadIdx.x];
    if (v < 0 || v >= (long long)N_NODES) d_flag = 1;
}

// K2: bucket edges by destination node
__global__ void k_bucket(const void* __restrict__ ei) {
    int e = blockIdx.x * blockDim.x + threadIdx.x;
    if (e >= N_EDGES) return;
    int c = d_flag ? ((const int*)ei)[N_EDGES + e]
                   : (int)((const long long*)ei)[N_EDGES + e];
    int pos = atomicAdd(&d_cursor[c], 1);
    if (pos < CAP) d_bucket[c * CAP + pos] = e;
}

// K2b: transpose + triple-split weights.  B'-slot pattern per k: [hi, lo, hi]
__global__ void k_prepW(const float* __restrict__ W1, const float* __restrict__ W2) {
    int i = blockIdx.x * blockDim.x + threadIdx.x;
    const int N1 = HID * DIN;
    if (i < N1) {
        int n = i / DIN, k = i % DIN;
        unsigned short h, l;
        split_u16(W1[(size_t)k * HID + n], h, l);
        unsigned short* p = d_W1p + (size_t)n * K1P + 3 * k;
        p[0] = h; p[1] = l; p[2] = h;
    } else if (i < N1 + NODE_OUT * HID) {
        int j = i - N1;
        int n = j / HID, k = j % HID;
        unsigned short h, l;
        split_u16(W2[(size_t)k * NODE_OUT + n], h, l);
        unsigned short* p = d_W2p + (size_t)n * K2P + 3 * k;
        p[0] = h; p[1] = l; p[2] = h;
    }
}

// ---------------------------------------------------------------------------
// K3: per-node reduce -> A' row (triple layout [hi, hi, lo] per k)
// ---------------------------------------------------------------------------
__global__ void __launch_bounds__(64) k_buildH(const float* __restrict__ x,
                                               const float* __restrict__ edge_attr) {
    __shared__ int se[CAP];
    __shared__ __align__(16) unsigned short rowbuf[K1P];
    const int n = blockIdx.x;
    const int f = threadIdx.x;

    const int total = d_cursor[n];
    const int ec = total < CAP ? total : CAP;
    for (int i = f; i < ec; i += 64) se[i] = d_bucket[n * CAP + i];
    __syncthreads();

    const float NEG_INF = __int_as_float(0xff800000u);
    float s0 = 0.f, s1 = 0.f, s2 = 0.f, s3 = 0.f;
    float m0 = NEG_INF, m1 = NEG_INF, m2 = NEG_INF, m3 = NEG_INF;

    int i = 0;
    for (; i + 4 <= ec; i += 4) {
        float v0 = __ldg(&edge_attr[(size_t)se[i + 0] * EDGE_OUT + f]);
        float v1 = __ldg(&edge_attr[(size_t)se[i + 1] * EDGE_OUT + f]);
        float v2 = __ldg(&edge_attr[(size_t)se[i + 2] * EDGE_OUT + f]);
        float v3 = __ldg(&edge_attr[(size_t)se[i + 3] * EDGE_OUT + f]);
        s0 += v0; s1 += v1; s2 += v2; s3 += v3;
        m0 = fmaxf(m0, v0); m1 = fmaxf(m1, v1);
        m2 = fmaxf(m2, v2); m3 = fmaxf(m3, v3);
    }
    for (; i < ec; i++) {
        float v = __ldg(&edge_attr[(size_t)se[i] * EDGE_OUT + f]);
        s0 += v; m0 = fmaxf(m0, v);
    }
    const float sum = (s0 + s1) + (s2 + s3);
    float mx = fmaxf(fmaxf(m0, m1), fmaxf(m2, m3));
    if (ec == 0) mx = 0.f;
    const float mean = sum / fmaxf((float)total, 1.f);

    // triple A'-pattern [hi, hi, lo]
    float vals[5];
    vals[0] = x[(size_t)n * NODE_IN + f];
    vals[1] = x[(size_t)n * NODE_IN + 64 + f];
    vals[2] = sum; vals[3] = mx; vals[4] = mean;
#pragma unroll
    for (int c5 = 0; c5 < 5; c5++) {
        int c = c5 * 64 + f;
        unsigned short h, l;
        split_u16(vals[c5], h, l);
        rowbuf[3 * c] = h; rowbuf[3 * c + 1] = h; rowbuf[3 * c + 2] = l;
    }
    __syncthreads();

    uint4* g = (uint4*)(d_A1 + (size_t)n * K1P);
    const uint4* s4 = (const uint4*)rowbuf;
    for (int w = f; w < K1P / 8; w += 64) g[w] = s4[w];   // 120 uint4
}

// ---------------------------------------------------------------------------
// K4/K5: bf16 mma.sync GEMM.  C = act(A' @ B'^T + bias)
// A': [MPAD][Kp] bf16 row-major.  B': [Ntot][Kp] bf16 row-major (K-contig).
// CTA tile 128x128, BK=32, 8 warps (2M x 4N -> 64x32 warp tiles), cp.async x2.
// MODE 0: relu + triple-split bf16 -> d_Hm.  MODE 1: fp32 + bias -> out.
// ---------------------------------------------------------------------------
#define SROW  80        // smem bytes per 32-half row (64B data + 16B pad)
#define STILE 10240     // 128 rows * 80B

template <int MODE>
__global__ void __launch_bounds__(256)
k_mma(const unsigned short* __restrict__ gA, const unsigned short* __restrict__ gB,
      const float* __restrict__ bias, void* __restrict__ outp, int Kp) {
    __shared__ __align__(16) char sm[40960];
    const int tid = threadIdx.x, L = tid & 31, wid = tid >> 5;
    const int wm = wid >> 2, wn = wid & 3;
    const int n0 = blockIdx.x * 128, row0 = blockIdx.y * 128;
    const uint32_t sb = smem_u32_(sm);

    float acc[4][4][4];
#pragma unroll
    for (int a = 0; a < 4; a++)
#pragma unroll
        for (int b = 0; b < 4; b++)
#pragma unroll
            for (int c = 0; c < 4; c++) acc[a][b][c] = 0.f;

    const int chk0 = tid, chk1 = tid + 256;
    const int r0c = chk0 >> 2, q0c = (chk0 & 3) * 16;
    const int r1c = chk1 >> 2, q1c = (chk1 & 3) * 16;

#define LOAD_STAGE(s, k0)                                                        \
    do {                                                                         \
        uint32_t Ab_ = sb + (s) * STILE, Bb_ = sb + 20480 + (s) * STILE;         \
        cpa16(Ab_ + r0c * SROW + q0c, gA + (size_t)(row0 + r0c) * Kp + (k0) + (q0c >> 1)); \
        cpa16(Ab_ + r1c * SROW + q1c, gA + (size_t)(row0 + r1c) * Kp + (k0) + (q1c >> 1)); \
        cpa16(Bb_ + r0c * SROW + q0c, gB + (size_t)(n0 + r0c) * Kp + (k0) + (q0c >> 1));   \
        cpa16(Bb_ + r1c * SROW + q1c, gB + (size_t)(n0 + r1c) * Kp + (k0) + (q1c >> 1));   \
    } while (0)

    const int NT = Kp >> 5;
    LOAD_STAGE(0, 0);
    CP_COMMIT();

    for (int kt = 0; kt < NT; kt++) {
        if (kt + 1 < NT) LOAD_STAGE((kt + 1) & 1, (kt + 1) << 5);
        CP_COMMIT();
        CP_WAIT1();
        __syncthreads();

        const int s = kt & 1;
        const uint32_t Ab = sb + s * STILE;
        const uint32_t Bb = sb + 20480 + s * STILE;
        const uint32_t aBase = Ab + (uint32_t)((wm * 64 + (L & 15)) * SROW + ((L >> 4) << 4));
        const uint32_t bBase = Bb + (uint32_t)((wn * 32 + (L & 7) + ((L >> 4) << 3)) * SROW
                                               + (((L >> 3) & 1) << 4));
#pragma unroll
        for (int ks = 0; ks < 2; ks++) {
            uint32_t afr[4][4], bfr[2][4];
#pragma unroll
            for (int mf = 0; mf < 4; mf++) LDSM4(afr[mf], aBase + mf * 16 * SROW + ks * 32);
#pragma unroll
            for (int nb = 0; nb < 2; nb++) LDSM4(bfr[nb], bBase + nb * 16 * SROW + ks * 32);
#pragma unroll
            for (int mf = 0; mf < 4; mf++)
#pragma unroll
                for (int nf = 0; nf < 4; nf++)
                    mma16816(acc[mf][nf], afr[mf], &bfr[nf >> 1][(nf & 1) * 2]);
        }
        __syncthreads();
    }

    if (MODE == 0) {
        // relu + triple [hi,hi,lo] bf16 into d_Hm rows (A' layout for GEMM2)
        unsigned short* gO = (unsigned short*)outp;
        float* st = (float*)sm;
#pragma unroll 1
        for (int half = 0; half < 2; half++) {
            if (wm == half) {
#pragma unroll
                for (int mf = 0; mf < 4; mf++)
#pragma unroll
                    for (int nf = 0; nf < 4; nf++) {
                        int r = mf * 16 + (L >> 2), c = wn * 32 + nf * 8 + (L & 3) * 2;
                        st[r * 128 + c]           = acc[mf][nf][0];
                        st[r * 128 + c + 1]       = acc[mf][nf][1];
                        st[(r + 8) * 128 + c]     = acc[mf][nf][2];
                        st[(r + 8) * 128 + c + 1] = acc[mf][nf][3];
                    }
            }
            __syncthreads();
            for (int idx = tid; idx < 64 * 48; idx += 256) {
                int r = idx / 48, w = idx % 48;
                uint4 pack;
                unsigned short* t8 = (unsigned short*)&pack;
#pragma unroll
                for (int q = 0; q < 8; q++) {
                    int sI = w * 8 + q, t = sI / 3, slot = sI - 3 * t;
                    float v = st[r * 128 + t] + __ldg(bias + n0 + t);
                    v = fmaxf(v, 0.f);
                    __nv_bfloat16 hb = __float2bfloat16(v);
                    t8[q] = (slot == 2)
                        ? __bfloat16_as_ushort(__float2bfloat16(v - __bfloat162float(hb)))
                        : __bfloat16_as_ushort(hb);
                }
                size_t gr = (size_t)(row0 + half * 64 + r);
                *(uint4*)((char*)(gO + gr * K2P + (size_t)n0 * 3) + w * 16) = pack;
            }
            __syncthreads();
        }
    } else {
        // fp32 + bias, row-guarded
        float* gO = (float*)outp;
#pragma unroll
        for (int mf = 0; mf < 4; mf++) {
            int r = row0 + wm * 64 + mf * 16 + (L >> 2);
#pragma unroll
            for (int nf = 0; nf < 4; nf++) {
                int c = n0 + wn * 32 + nf * 8 + (L & 3) * 2;
                float b0 = __ldg(bias + c), b1 = __ldg(bias + c + 1);
                if (r < N_NODES) {
                    gO[(size_t)r * NODE_OUT + c]     = acc[mf][nf][0] + b0;
                    gO[(size_t)r * NODE_OUT + c + 1] = acc[mf][nf][1] + b1;
                }
                if (r + 8 < N_NODES) {
                    gO[(size_t)(r + 8) * NODE_OUT + c]     = acc[mf][nf][2] + b0;
                    gO[(size_t)(r + 8) * NODE_OUT + c + 1] = acc[mf][nf][3] + b1;
                }
            }
        }
    }
#undef LOAD_STAGE
}

// ---------------------------------------------------------------------------
// Host launcher (graph-capturable: kernel launches only)
// ---------------------------------------------------------------------------
extern "C" void kernel_launch(void* const* d_in, const int* in_sizes, int n_in,
                              void* d_out, int out_size) {
    const float* x         = (const float*)d_in[0];
    const void*  ei        = d_in[1];
    const float* edge_attr = (const float*)d_in[2];
    const float* W1 = (const float*)d_in[5];
    const float* b1 = (const float*)d_in[6];
    const float* W2 = (const float*)d_in[7];
    const float* b2 = (const float*)d_in[8];
    float* out = (float*)d_out;

    void *pA1, *pHm, *pW1p, *pW2p;
    cudaGetSymbolAddress(&pA1, d_A1);
    cudaGetSymbolAddress(&pHm, d_Hm);
    cudaGetSymbolAddress(&pW1p, d_W1p);
    cudaGetSymbolAddress(&pW2p, d_W2p);

    k_init<<<(N_NODES + 255) / 256, 256>>>();
    k_probe<<<1, 256>>>(ei);
    k_bucket<<<(N_EDGES + 255) / 256, 256>>>(ei);
    {
        const int tot = HID * DIN + NODE_OUT * HID;
        k_prepW<<<(tot + 255) / 256, 256>>>(W1, W2);
    }
    k_buildH<<<N_NODES, 64>>>(x, edge_attr);

    // GEMM1: [MPAD,960] x [512,960]^T -> relu -> triple bf16 Hm
    k_mma<0><<<dim3(HID / 128, MPAD / 128), 256>>>(
        (const unsigned short*)pA1, (const unsigned short*)pW1p, b1, pHm, K1P);
    // GEMM2: [MPAD,1536] x [128,1536]^T -> fp32 out
    k_mma<1><<<dim3(NODE_OUT / 128, MPAD / 128), 256>>>(
        (const unsigned short*)pHm, (const unsigned short*)pW2p, b2, out, K2P);
}

// round 5
// speedup vs baseline: 1.8502x; 1.0339x over previous
#include <cuda_runtime.h>
#include <cuda_bf16.h>
#include <cstdint>

// ---------------------------------------------------------------------------
// Problem constants
// ---------------------------------------------------------------------------
#define N_NODES  50000
#define N_EDGES  800000
#define NODE_IN  128
#define EDGE_OUT 64
#define DIN      320
#define HID      512
#define NODE_OUT 128
#define CAP      96
#define MPAD     50048          // 391 * 128
#define K1P      (DIN * 3)      // 960  (triple-expanded K for GEMM1)
#define K2P      (HID * 3)      // 1536 (triple-expanded K for GEMM2)

// ---------------------------------------------------------------------------
// Static device scratch (__device__ globals only; no allocations)
// ---------------------------------------------------------------------------
__device__ int d_flag;
__device__ int d_cursor[N_NODES];
__device__ int d_bucket[N_NODES * CAP];
__device__ __align__(16) unsigned short d_A1[(size_t)MPAD * K1P];     // A' for GEMM1
__device__ __align__(16) unsigned short d_Hm[(size_t)MPAD * K2P];     // A' for GEMM2
__device__ __align__(16) unsigned short d_W1p[HID * K1P];             // B' (W1^T triple)
__device__ __align__(16) unsigned short d_W2p[NODE_OUT * K2P];        // B' (W2^T triple)

// ---------------------------------------------------------------------------
// Helpers
// ---------------------------------------------------------------------------
__device__ __forceinline__ uint32_t smem_u32_(const void* p) {
    uint32_t a;
    asm("{ .reg .u64 t; cvta.to.shared.u64 t, %1; cvt.u32.u64 %0, t; }" : "=r"(a) : "l"(p));
    return a;
}

// bf16 hi/lo split: v ~= hi + lo, |err| <= 2^-17 |v|
__device__ __forceinline__ void split_u16(float v, unsigned short& h, unsigned short& l) {
    __nv_bfloat16 hb = __float2bfloat16(v);
    __nv_bfloat16 lb = __float2bfloat16(v - __bfloat162float(hb));
    h = __bfloat16_as_ushort(hb);
    l = __bfloat16_as_ushort(lb);
}

__device__ __forceinline__ void cpa16(uint32_t s, const void* g) {
    asm volatile("cp.async.cg.shared.global [%0], [%1], 16;"
                 :: "r"(s), "l"(__cvta_generic_to_global(g)));
}
#define CP_COMMIT() asm volatile("cp.async.commit_group;")
#define CP_WAIT2()  asm volatile("cp.async.wait_group 2;")

#define LDSM4(r, a)                                                          \
    asm volatile("ldmatrix.sync.aligned.m8n8.x4.shared.b16 {%0,%1,%2,%3}, [%4];" \
        : "=r"((r)[0]), "=r"((r)[1]), "=r"((r)[2]), "=r"((r)[3]) : "r"(a))

__device__ __forceinline__ void mma16816(float* c, const uint32_t* a, const uint32_t* b) {
    asm volatile(
        "mma.sync.aligned.m16n8k16.row.col.f32.bf16.bf16.f32 "
        "{%0,%1,%2,%3}, {%4,%5,%6,%7}, {%8,%9}, {%0,%1,%2,%3};"
        : "+f"(c[0]), "+f"(c[1]), "+f"(c[2]), "+f"(c[3])
        : "r"(a[0]), "r"(a[1]), "r"(a[2]), "r"(a[3]), "r"(b[0]), "r"(b[1]));
}

// ---------------------------------------------------------------------------
// K0: init cursors + flag
// ---------------------------------------------------------------------------
__global__ void k_init() {
    int i = blockIdx.x * blockDim.x + threadIdx.x;
    if (i < N_NODES) d_cursor[i] = 0;
    if (i == 0) d_flag = 0;
}

// K1: dtype probe (int64 vs int32 edge_index)
__global__ void k_probe(const void* __restrict__ ei) {
    const long long v = ((const long long*)ei)[threadIdx.x];
    if (v < 0 || v >= (long long)N_NODES) d_flag = 1;
}

// K2: bucket edges by destination node
__global__ void k_bucket(const void* __restrict__ ei) {
    int e = blockIdx.x * blockDim.x + threadIdx.x;
    if (e >= N_EDGES) return;
    int c = d_flag ? ((const int*)ei)[N_EDGES + e]
                   : (int)((const long long*)ei)[N_EDGES + e];
    int pos = atomicAdd(&d_cursor[c], 1);
    if (pos < CAP) d_bucket[c * CAP + pos] = e;
}

// K2b: transpose + triple-split weights.  B'-slot pattern per k: [hi, lo, hi]
__global__ void k_prepW(const float* __restrict__ W1, const float* __restrict__ W2) {
    int i = blockIdx.x * blockDim.x + threadIdx.x;
    const int N1 = HID * DIN;
    if (i < N1) {
        int n = i / DIN, k = i % DIN;
        unsigned short h, l;
        split_u16(W1[(size_t)k * HID + n], h, l);
        unsigned short* p = d_W1p + (size_t)n * K1P + 3 * k;
        p[0] = h; p[1] = l; p[2] = h;
    } else if (i < N1 + NODE_OUT * HID) {
        int j = i - N1;
        int n = j / HID, k = j % HID;
        unsigned short h, l;
        split_u16(W2[(size_t)k * NODE_OUT + n], h, l);
        unsigned short* p = d_W2p + (size_t)n * K2P + 3 * k;
        p[0] = h; p[1] = l; p[2] = h;
    }
}

// ---------------------------------------------------------------------------
// K3: per-node reduce -> A' row (triple layout [hi, hi, lo] per k)
// Runs over MPAD rows; padding rows (n >= N_NODES) are zero-filled.
// ---------------------------------------------------------------------------
__global__ void __launch_bounds__(64) k_buildH(const float* __restrict__ x,
                                               const float* __restrict__ edge_attr) {
    __shared__ int se[CAP];
    __shared__ __align__(16) unsigned short rowbuf[K1P];
    const int n = blockIdx.x;
    const int f = threadIdx.x;

    if (n >= N_NODES) {            // zero padding rows for determinism
        uint4* g = (uint4*)(d_A1 + (size_t)n * K1P);
        uint4 z = make_uint4(0, 0, 0, 0);
        for (int w = f; w < K1P / 8; w += 64) g[w] = z;
        return;
    }

    const int total = d_cursor[n];
    const int ec = total < CAP ? total : CAP;
    for (int i = f; i < ec; i += 64) se[i] = d_bucket[n * CAP + i];
    __syncthreads();

    const float NEG_INF = __int_as_float(0xff800000u);
    float s0 = 0.f, s1 = 0.f, s2 = 0.f, s3 = 0.f;
    float m0 = NEG_INF, m1 = NEG_INF, m2 = NEG_INF, m3 = NEG_INF;

    int i = 0;
    for (; i + 4 <= ec; i += 4) {
        float v0 = __ldg(&edge_attr[(size_t)se[i + 0] * EDGE_OUT + f]);
        float v1 = __ldg(&edge_attr[(size_t)se[i + 1] * EDGE_OUT + f]);
        float v2 = __ldg(&edge_attr[(size_t)se[i + 2] * EDGE_OUT + f]);
        float v3 = __ldg(&edge_attr[(size_t)se[i + 3] * EDGE_OUT + f]);
        s0 += v0; s1 += v1; s2 += v2; s3 += v3;
        m0 = fmaxf(m0, v0); m1 = fmaxf(m1, v1);
        m2 = fmaxf(m2, v2); m3 = fmaxf(m3, v3);
    }
    for (; i < ec; i++) {
        float v = __ldg(&edge_attr[(size_t)se[i] * EDGE_OUT + f]);
        s0 += v; m0 = fmaxf(m0, v);
    }
    const float sum = (s0 + s1) + (s2 + s3);
    float mx = fmaxf(fmaxf(m0, m1), fmaxf(m2, m3));
    if (ec == 0) mx = 0.f;
    const float mean = sum / fmaxf((float)total, 1.f);

    float vals[5];
    vals[0] = x[(size_t)n * NODE_IN + f];
    vals[1] = x[(size_t)n * NODE_IN + 64 + f];
    vals[2] = sum; vals[3] = mx; vals[4] = mean;
#pragma unroll
    for (int c5 = 0; c5 < 5; c5++) {
        int c = c5 * 64 + f;
        unsigned short h, l;
        split_u16(vals[c5], h, l);
        rowbuf[3 * c] = h; rowbuf[3 * c + 1] = h; rowbuf[3 * c + 2] = l;
    }
    __syncthreads();

    uint4* g = (uint4*)(d_A1 + (size_t)n * K1P);
    const uint4* s4 = (const uint4*)rowbuf;
    for (int w = f; w < K1P / 8; w += 64) g[w] = s4[w];
}

// ---------------------------------------------------------------------------
// K4/K5: bf16 mma.sync GEMM with 4-stage cp.async ring.
// C = act(A' @ B'^T + bias).  CTA tile 128x128, BK=32, 8 warps (2Mx4N).
// One __syncthreads per K-iteration; stage k covered by 3 compute iterations.
// MODE 0: relu + triple-split bf16 -> d_Hm.  MODE 1: fp32 + bias -> out.
// ---------------------------------------------------------------------------
#define SROW   80                // smem bytes per 32-half row (64B data + 16B pad)
#define STILE  10240             // 128 rows * 80B
#define STAGEB 20480             // A tile + B tile per stage
#define NSTAGE 4
#define SMEM_DYN (NSTAGE * STAGEB)   // 81920

template <int MODE>
__global__ void __launch_bounds__(256, 2)
k_mma(const unsigned short* __restrict__ gA, const unsigned short* __restrict__ gB,
      const float* __restrict__ bias, void* __restrict__ outp, int Kp) {
    extern __shared__ __align__(16) char sm[];
    const int tid = threadIdx.x, L = tid & 31, wid = tid >> 5;
    const int wm = wid >> 2, wn = wid & 3;
    const int n0 = blockIdx.x * 128, row0 = blockIdx.y * 128;
    const uint32_t sb = smem_u32_(sm);

    float acc[4][4][4];
#pragma unroll
    for (int a = 0; a < 4; a++)
#pragma unroll
        for (int b = 0; b < 4; b++)
#pragma unroll
            for (int c = 0; c < 4; c++) acc[a][b][c] = 0.f;

    const int chk0 = tid, chk1 = tid + 256;
    const int r0c = chk0 >> 2, q0c = (chk0 & 3) * 16;
    const int r1c = chk1 >> 2, q1c = (chk1 & 3) * 16;

#define LOAD_STAGE(s, k0)                                                        \
    do {                                                                         \
        uint32_t Ab_ = sb + (s) * STAGEB, Bb_ = Ab_ + STILE;                     \
        cpa16(Ab_ + r0c * SROW + q0c, gA + (size_t)(row0 + r0c) * Kp + (k0) + (q0c >> 1)); \
        cpa16(Ab_ + r1c * SROW + q1c, gA + (size_t)(row0 + r1c) * Kp + (k0) + (q1c >> 1)); \
        cpa16(Bb_ + r0c * SROW + q0c, gB + (size_t)(n0 + r0c) * Kp + (k0) + (q0c >> 1));   \
        cpa16(Bb_ + r1c * SROW + q1c, gB + (size_t)(n0 + r1c) * Kp + (k0) + (q1c >> 1));   \
    } while (0)

    const int NT = Kp >> 5;
    // prologue: 3 stages in flight
#pragma unroll
    for (int p = 0; p < 3; p++) {
        LOAD_STAGE(p, p << 5);
        CP_COMMIT();
    }

    for (int kt = 0; kt < NT; kt++) {
        CP_WAIT2();                 // oldest group (stage kt) complete
        __syncthreads();            // all warps done with the slot being reused

        if (kt + 3 < NT) LOAD_STAGE((kt + 3) & (NSTAGE - 1), (kt + 3) << 5);
        CP_COMMIT();

        const int s = kt & (NSTAGE - 1);
        const uint32_t Ab = sb + s * STAGEB;
        const uint32_t Bb = Ab + STILE;
        const uint32_t aBase = Ab + (uint32_t)((wm * 64 + (L & 15)) * SROW + ((L >> 4) << 4));
        const uint32_t bBase = Bb + (uint32_t)((wn * 32 + (L & 7) + ((L >> 4) << 3)) * SROW
                                               + (((L >> 3) & 1) << 4));
#pragma unroll
        for (int ks = 0; ks < 2; ks++) {
            uint32_t afr[4][4], bfr[2][4];
#pragma unroll
            for (int mf = 0; mf < 4; mf++) LDSM4(afr[mf], aBase + mf * 16 * SROW + ks * 32);
#pragma unroll
            for (int nb = 0; nb < 2; nb++) LDSM4(bfr[nb], bBase + nb * 16 * SROW + ks * 32);
#pragma unroll
            for (int mf = 0; mf < 4; mf++)
#pragma unroll
                for (int nf = 0; nf < 4; nf++)
                    mma16816(acc[mf][nf], afr[mf], &bfr[nf >> 1][(nf & 1) * 2]);
        }
    }
    __syncthreads();

    if (MODE == 0) {
        // relu + triple [hi,hi,lo] bf16 into d_Hm rows (A' layout for GEMM2)
        unsigned short* gO = (unsigned short*)outp;
        float* st = (float*)sm;
#pragma unroll 1
        for (int half = 0; half < 2; half++) {
            if (wm == half) {
#pragma unroll
                for (int mf = 0; mf < 4; mf++)
#pragma unroll
                    for (int nf = 0; nf < 4; nf++) {
                        int r = mf * 16 + (L >> 2), c = wn * 32 + nf * 8 + (L & 3) * 2;
                        st[r * 128 + c]           = acc[mf][nf][0];
                        st[r * 128 + c + 1]       = acc[mf][nf][1];
                        st[(r + 8) * 128 + c]     = acc[mf][nf][2];
                        st[(r + 8) * 128 + c + 1] = acc[mf][nf][3];
                    }
            }
            __syncthreads();
            for (int idx = tid; idx < 64 * 48; idx += 256) {
                int r = idx / 48, w = idx % 48;
                uint4 pack;
                unsigned short* t8 = (unsigned short*)&pack;
#pragma unroll
                for (int q = 0; q < 8; q++) {
                    int sI = w * 8 + q, t = sI / 3, slot = sI - 3 * t;
                    float v = st[r * 128 + t] + __ldg(bias + n0 + t);
                    v = fmaxf(v, 0.f);
                    __nv_bfloat16 hb = __float2bfloat16(v);
                    t8[q] = (slot == 2)
                        ? __bfloat16_as_ushort(__float2bfloat16(v - __bfloat162float(hb)))
                        : __bfloat16_as_ushort(hb);
                }
                size_t gr = (size_t)(row0 + half * 64 + r);
                *(uint4*)((char*)(gO + gr * K2P + (size_t)n0 * 3) + w * 16) = pack;
            }
            __syncthreads();
        }
    } else {
        // fp32 + bias, row-guarded
        float* gO = (float*)outp;
#pragma unroll
        for (int mf = 0; mf < 4; mf++) {
            int r = row0 + wm * 64 + mf * 16 + (L >> 2);
#pragma unroll
            for (int nf = 0; nf < 4; nf++) {
                int c = n0 + wn * 32 + nf * 8 + (L & 3) * 2;
                float b0 = __ldg(bias + c), b1 = __ldg(bias + c + 1);
                if (r < N_NODES) {
                    gO[(size_t)r * NODE_OUT + c]     = acc[mf][nf][0] + b0;
                    gO[(size_t)r * NODE_OUT + c + 1] = acc[mf][nf][1] + b1;
                }
                if (r + 8 < N_NODES) {
                    gO[(size_t)(r + 8) * NODE_OUT + c]     = acc[mf][nf][2] + b0;
                    gO[(size_t)(r + 8) * NODE_OUT + c + 1] = acc[mf][nf][3] + b1;
                }
            }
        }
    }
#undef LOAD_STAGE
}

// ---------------------------------------------------------------------------
// Host launcher (graph-capturable: kernel launches only)
// ---------------------------------------------------------------------------
extern "C" void kernel_launch(void* const* d_in, const int* in_sizes, int n_in,
                              void* d_out, int out_size) {
    const float* x         = (const float*)d_in[0];
    const void*  ei        = d_in[1];
    const float* edge_attr = (const float*)d_in[2];
    const float* W1 = (const float*)d_in[5];
    const float* b1 = (const float*)d_in[6];
    const float* W2 = (const float*)d_in[7];
    const float* b2 = (const float*)d_in[8];
    float* out = (float*)d_out;

    void *pA1, *pHm, *pW1p, *pW2p;
    cudaGetSymbolAddress(&pA1, d_A1);
    cudaGetSymbolAddress(&pHm, d_Hm);
    cudaGetSymbolAddress(&pW1p, d_W1p);
    cudaGetSymbolAddress(&pW2p, d_W2p);

    cudaFuncSetAttribute(k_mma<0>, cudaFuncAttributeMaxDynamicSharedMemorySize, SMEM_DYN);
    cudaFuncSetAttribute(k_mma<1>, cudaFuncAttributeMaxDynamicSharedMemorySize, SMEM_DYN);

    k_init<<<(N_NODES + 255) / 256, 256>>>();
    k_probe<<<1, 256>>>(ei);
    k_bucket<<<(N_EDGES + 255) / 256, 256>>>(ei);
    {
        const int tot = HID * DIN + NODE_OUT * HID;
        k_prepW<<<(tot + 255) / 256, 256>>>(W1, W2);
    }
    k_buildH<<<MPAD / 128 * 128, 64>>>(x, edge_attr);   // MPAD rows (incl. zero pad)

    // GEMM1: [MPAD,960] x [512,960]^T -> relu -> triple bf16 Hm
    k_mma<0><<<dim3(HID / 128, MPAD / 128), 256, SMEM_DYN>>>(
        (const unsigned short*)pA1, (const unsigned short*)pW1p, b1, pHm, K1P);
    // GEMM2: [MPAD,1536] x [128,1536]^T -> fp32 out
    k_mma<1><<<dim3(NODE_OUT / 128, MPAD / 128), 256, SMEM_DYN>>>(
        (const unsigned short*)pHm, (const unsigned short*)pW2p, b2, out, K2P);
}

// round 7
// speedup vs baseline: 2.6052x; 1.4080x over previous
#include <cuda_runtime.h>
#include <cuda_fp16.h>
#include <cstdint>

// ---------------------------------------------------------------------------
// Problem constants
// ---------------------------------------------------------------------------
#define N_NODES  50000
#define N_EDGES  800000
#define NODE_IN  128
#define EDGE_OUT 64
#define DIN      320
#define HID      512
#define NODE_OUT 128
#define CAP      96
#define MPAD     50048          // 391 * 128 (also divisible by 64)
#define K1E      (DIN * 2)      // 640  (2-term expanded K for GEMM1)
#define K2E      (HID * 2)      // 1024 (2-term expanded K for GEMM2)

// ---------------------------------------------------------------------------
// Static device scratch (__device__ globals only; no allocations)
// ---------------------------------------------------------------------------
__device__ int d_flag;
__device__ int d_cursor[N_NODES];
__device__ int d_bucket[N_NODES * CAP];
__device__ __align__(16) unsigned short d_A1[(size_t)MPAD * K1E];     // A' GEMM1 [hi,lo]
__device__ __align__(16) unsigned short d_Hm[(size_t)MPAD * K2E];     // A' GEMM2 [hi,lo]
__device__ __align__(16) unsigned short d_W1p[HID * K1E];             // W1^T dup [Wh,Wh]
__device__ __align__(16) unsigned short d_W2p[NODE_OUT * K2E];        // W2^T dup [Wh,Wh]

// ---------------------------------------------------------------------------
// Helpers
// ---------------------------------------------------------------------------
__device__ __forceinline__ uint32_t smem_u32_(const void* p) {
    uint32_t a;
    asm("{ .reg .u64 t; cvta.to.shared.u64 t, %1; cvt.u32.u64 %0, t; }" : "=r"(a) : "l"(p));
    return a;
}

// fp16 hi/lo split: v ~= hi + lo, residual ~2^-22 |v|
__device__ __forceinline__ void split_h16(float v, unsigned short& h, unsigned short& l) {
    __half hb = __float2half_rn(v);
    __half lb = __float2half_rn(v - __half2float(hb));
    h = __half_as_ushort(hb);
    l = __half_as_ushort(lb);
}

__device__ __forceinline__ void cpa16(uint32_t s, const void* g) {
    asm volatile("cp.async.cg.shared.global [%0], [%1], 16;"
                 :: "r"(s), "l"(__cvta_generic_to_global(g)));
}
#define CP_COMMIT() asm volatile("cp.async.commit_group;")
#define CP_WAIT2()  asm volatile("cp.async.wait_group 2;")

#define LDSM4(r, a)                                                          \
    asm volatile("ldmatrix.sync.aligned.m8n8.x4.shared.b16 {%0,%1,%2,%3}, [%4];" \
        : "=r"((r)[0]), "=r"((r)[1]), "=r"((r)[2]), "=r"((r)[3]) : "r"(a))

__device__ __forceinline__ void mma16816(float* c, const uint32_t* a, const uint32_t* b) {
    asm volatile(
        "mma.sync.aligned.m16n8k16.row.col.f32.f16.f16.f32 "
        "{%0,%1,%2,%3}, {%4,%5,%6,%7}, {%8,%9}, {%0,%1,%2,%3};"
        : "+f"(c[0]), "+f"(c[1]), "+f"(c[2]), "+f"(c[3])
        : "r"(a[0]), "r"(a[1]), "r"(a[2]), "r"(a[3]), "r"(b[0]), "r"(b[1]));
}

// ---------------------------------------------------------------------------
// K0: init cursors + flag
// ---------------------------------------------------------------------------
__global__ void k_init() {
    int i = blockIdx.x * blockDim.x + threadIdx.x;
    if (i < N_NODES) d_cursor[i] = 0;
    if (i == 0) d_flag = 0;
}

// K1: dtype probe (int64 vs int32 edge_index)
__global__ void k_probe(const void* __restrict__ ei) {
    const long long v = ((const long long*)ei)[threadIdx.x];
    if (v < 0 || v >= (long long)N_NODES) d_flag = 1;
}

// K2: bucket edges by destination node
__global__ void k_bucket(const void* __restrict__ ei) {
    int e = blockIdx.x * blockDim.x + threadIdx.x;
    if (e >= N_EDGES) return;
    int c = d_flag ? ((const int*)ei)[N_EDGES + e]
                   : (int)((const long long*)ei)[N_EDGES + e];
    int pos = atomicAdd(&d_cursor[c], 1);
    if (pos < CAP) d_bucket[c * CAP + pos] = e;
}

// K2b: transpose weights, round to fp16, duplicate into both k'-slots
__global__ void k_prepW(const float* __restrict__ W1, const float* __restrict__ W2) {
    int i = blockIdx.x * blockDim.x + threadIdx.x;
    const int N1 = HID * DIN;
    if (i < N1) {
        int n = i / DIN, k = i % DIN;
        unsigned short w = __half_as_ushort(__float2half_rn(W1[(size_t)k * HID + n]));
        unsigned short* p = d_W1p + (size_t)n * K1E + 2 * k;
        p[0] = w; p[1] = w;
    } else if (i < N1 + NODE_OUT * HID) {
        int j = i - N1;
        int n = j / HID, k = j % HID;
        unsigned short w = __half_as_ushort(__float2half_rn(W2[(size_t)k * NODE_OUT + n]));
        unsigned short* p = d_W2p + (size_t)n * K2E + 2 * k;
        p[0] = w; p[1] = w;
    }
}

// ---------------------------------------------------------------------------
// K3: per-node reduce -> A' row ([hi,lo] fp16 per feature)
// Runs over MPAD rows; padding rows (n >= N_NODES) are zero-filled.
// ---------------------------------------------------------------------------
__global__ void __launch_bounds__(64) k_buildH(const float* __restrict__ x,
                                               const float* __restrict__ edge_attr) {
    __shared__ int se[CAP];
    __shared__ __align__(16) unsigned short rowbuf[K1E];
    const int n = blockIdx.x;
    const int f = threadIdx.x;

    if (n >= N_NODES) {            // zero padding rows for determinism
        uint4* g = (uint4*)(d_A1 + (size_t)n * K1E);
        uint4 z = make_uint4(0, 0, 0, 0);
        for (int w = f; w < K1E / 8; w += 64) g[w] = z;
        return;
    }

    const int total = d_cursor[n];
    const int ec = total < CAP ? total : CAP;
    for (int i = f; i < ec; i += 64) se[i] = d_bucket[n * CAP + i];
    __syncthreads();

    const float NEG_INF = __int_as_float(0xff800000u);
    float s0 = 0.f, s1 = 0.f, s2 = 0.f, s3 = 0.f;
    float m0 = NEG_INF, m1 = NEG_INF, m2 = NEG_INF, m3 = NEG_INF;

    int i = 0;
    for (; i + 4 <= ec; i += 4) {
        float v0 = __ldg(&edge_attr[(size_t)se[i + 0] * EDGE_OUT + f]);
        float v1 = __ldg(&edge_attr[(size_t)se[i + 1] * EDGE_OUT + f]);
        float v2 = __ldg(&edge_attr[(size_t)se[i + 2] * EDGE_OUT + f]);
        float v3 = __ldg(&edge_attr[(size_t)se[i + 3] * EDGE_OUT + f]);
        s0 += v0; s1 += v1; s2 += v2; s3 += v3;
        m0 = fmaxf(m0, v0); m1 = fmaxf(m1, v1);
        m2 = fmaxf(m2, v2); m3 = fmaxf(m3, v3);
    }
    for (; i < ec; i++) {
        float v = __ldg(&edge_attr[(size_t)se[i] * EDGE_OUT + f]);
        s0 += v; m0 = fmaxf(m0, v);
    }
    const float sum = (s0 + s1) + (s2 + s3);
    float mx = fmaxf(fmaxf(m0, m1), fmaxf(m2, m3));
    if (ec == 0) mx = 0.f;
    const float mean = sum / fmaxf((float)total, 1.f);

    float vals[5];
    vals[0] = x[(size_t)n * NODE_IN + f];
    vals[1] = x[(size_t)n * NODE_IN + 64 + f];
    vals[2] = sum; vals[3] = mx; vals[4] = mean;
#pragma unroll
    for (int c5 = 0; c5 < 5; c5++) {
        int c = c5 * 64 + f;
        split_h16(vals[c5], rowbuf[2 * c], rowbuf[2 * c + 1]);
    }
    __syncthreads();

    uint4* g = (uint4*)(d_A1 + (size_t)n * K1E);
    const uint4* s4 = (const uint4*)rowbuf;
    for (int w = f; w < K1E / 8; w += 64) g[w] = s4[w];   // 80 uint4
}

// ---------------------------------------------------------------------------
// K4/K5: fp16 mma.sync GEMM with 4-stage cp.async ring.
// C = act(A' @ B'^T + bias).  BK=32 k'-units, 8 warps.
// MODE 0: CTA 128x128 (2Mx4N warps), relu + [hi,lo] fp16 -> d_Hm.
// MODE 1: CTA  64x128 (2Mx4N, 32-row warp tiles), fp32 + bias -> out.
// ---------------------------------------------------------------------------
#define SROW   80                // smem bytes per 32-half row (64B data + 16B pad)
#define NSTAGE 4

template <int MODE>
__global__ void __launch_bounds__(256, 2)
k_mma(const unsigned short* __restrict__ gA, const unsigned short* __restrict__ gB,
      const float* __restrict__ bias, void* __restrict__ outp, int Kp) {
    constexpr int MT   = (MODE == 0) ? 128 : 64;     // M tile
    constexpr int MFR  = (MODE == 0) ? 4 : 2;        // 16-row frags per warp
    constexpr int ATB  = MT * SROW;                  // A tile bytes
    constexpr int STB  = ATB + 128 * SROW;           // stage bytes (A + B)

    extern __shared__ __align__(16) char sm[];
    const int tid = threadIdx.x, L = tid & 31, wid = tid >> 5;
    const int wm = wid >> 2, wn = wid & 3;
    const int n0 = blockIdx.x * 128, row0 = blockIdx.y * MT;
    const uint32_t sb = smem_u32_(sm);

    float acc[MFR][4][4];
#pragma unroll
    for (int a = 0; a < MFR; a++)
#pragma unroll
        for (int b = 0; b < 4; b++)
#pragma unroll
            for (int c = 0; c < 4; c++) acc[a][b][c] = 0.f;

    const int r0c = tid >> 2, q0c = (tid & 3) * 16;                 // chunk 0
    const int r1c = (tid + 256) >> 2, q1c = ((tid + 256) & 3) * 16; // chunk 1

#define LOAD_STAGE(s, k0)                                                        \
    do {                                                                         \
        uint32_t Ab_ = sb + (s) * STB, Bb_ = Ab_ + ATB;                          \
        cpa16(Ab_ + r0c * SROW + q0c, gA + (size_t)(row0 + r0c) * Kp + (k0) + (q0c >> 1)); \
        if constexpr (MT == 128)                                                 \
            cpa16(Ab_ + r1c * SROW + q1c, gA + (size_t)(row0 + r1c) * Kp + (k0) + (q1c >> 1)); \
        cpa16(Bb_ + r0c * SROW + q0c, gB + (size_t)(n0 + r0c) * Kp + (k0) + (q0c >> 1));   \
        cpa16(Bb_ + r1c * SROW + q1c, gB + (size_t)(n0 + r1c) * Kp + (k0) + (q1c >> 1));   \
    } while (0)

    const int NT = Kp >> 5;
#pragma unroll
    for (int p = 0; p < 3; p++) {      // prologue: 3 stages in flight
        LOAD_STAGE(p, p << 5);
        CP_COMMIT();
    }

    for (int kt = 0; kt < NT; kt++) {
        CP_WAIT2();
        __syncthreads();

        if (kt + 3 < NT) LOAD_STAGE((kt + 3) & (NSTAGE - 1), (kt + 3) << 5);
        CP_COMMIT();

        const int s = kt & (NSTAGE - 1);
        const uint32_t Ab = sb + s * STB;
        const uint32_t Bb = Ab + ATB;
        const uint32_t aBase = Ab + (uint32_t)((wm * (MFR * 16) + (L & 15)) * SROW + ((L >> 4) << 4));
        const uint32_t bBase = Bb + (uint32_t)((wn * 32 + (L & 7) + ((L >> 4) << 3)) * SROW
                                               + (((L >> 3) & 1) << 4));
#pragma unroll
        for (int ks = 0; ks < 2; ks++) {
            uint32_t afr[MFR][4], bfr[2][4];
#pragma unroll
            for (int mf = 0; mf < MFR; mf++) LDSM4(afr[mf], aBase + mf * 16 * SROW + ks * 32);
#pragma unroll
            for (int nb = 0; nb < 2; nb++) LDSM4(bfr[nb], bBase + nb * 16 * SROW + ks * 32);
#pragma unroll
            for (int mf = 0; mf < MFR; mf++)
#pragma unroll
                for (int nf = 0; nf < 4; nf++)
                    mma16816(acc[mf][nf], afr[mf], &bfr[nf >> 1][(nf & 1) * 2]);
        }
    }
    __syncthreads();

    if (MODE == 0) {
        // relu + [hi,lo] fp16 into d_Hm rows (A' layout for GEMM2)
        unsigned short* gO = (unsigned short*)outp;
        float* st = (float*)sm;
#pragma unroll 1
        for (int half = 0; half < 2; half++) {
            if (wm == half) {
#pragma unroll
                for (int mf = 0; mf < MFR; mf++)
#pragma unroll
                    for (int nf = 0; nf < 4; nf++) {
                        int r = mf * 16 + (L >> 2), c = wn * 32 + nf * 8 + (L & 3) * 2;
                        st[r * 128 + c]           = acc[mf][nf][0];
                        st[r * 128 + c + 1]       = acc[mf][nf][1];
                        st[(r + 8) * 128 + c]     = acc[mf][nf][2];
                        st[(r + 8) * 128 + c + 1] = acc[mf][nf][3];
                    }
            }
            __syncthreads();
            for (int idx = tid; idx < 64 * 32; idx += 256) {
                int r = idx >> 5, w = idx & 31;          // 32 uint4 per row
                uint4 pack;
                unsigned short* t8 = (unsigned short*)&pack;
#pragma unroll
                for (int q = 0; q < 8; q++) {
                    int sI = w * 8 + q, t = sI >> 1, slot = sI & 1;
                    float v = st[r * 128 + t] + __ldg(bias + n0 + t);
                    v = fmaxf(v, 0.f);
                    __half hb = __float2half_rn(v);
                    t8[q] = slot ? __half_as_ushort(__float2half_rn(v - __half2float(hb)))
                                 : __half_as_ushort(hb);
                }
                size_t gr = (size_t)(row0 + half * 64 + r);
                *(uint4*)((char*)(gO + gr * K2E + (size_t)n0 * 2) + w * 16) = pack;
            }
            __syncthreads();
        }
    } else {
        // fp32 + bias, row-guarded
        float* gO = (float*)outp;
#pragma unroll
        for (int mf = 0; mf < MFR; mf++) {
            int r = row0 + wm * (MFR * 16) + mf * 16 + (L >> 2);
#pragma unroll
            for (int nf = 0; nf < 4; nf++) {
                int c = n0 + wn * 32 + nf * 8 + (L & 3) * 2;
                float b0 = __ldg(bias + c), b1 = __ldg(bias + c + 1);
                if (r < N_NODES) {
                    gO[(size_t)r * NODE_OUT + c]     = acc[mf][nf][0] + b0;
                    gO[(size_t)r * NODE_OUT + c + 1] = acc[mf][nf][1] + b1;
                }
                if (r + 8 < N_NODES) {
                    gO[(size_t)(r + 8) * NODE_OUT + c]     = acc[mf][nf][2] + b0;
                    gO[(size_t)(r + 8) * NODE_OUT + c + 1] = acc[mf][nf][3] + b1;
                }
            }
        }
    }
#undef LOAD_STAGE
}

// ---------------------------------------------------------------------------
// Host launcher (graph-capturable: kernel launches only)
// ---------------------------------------------------------------------------
extern "C" void kernel_launch(void* const* d_in, const int* in_sizes, int n_in,
                              void* d_out, int out_size) {
    const float* x         = (const float*)d_in[0];
    const void*  ei        = d_in[1];
    const float* edge_attr = (const float*)d_in[2];
    const float* W1 = (const float*)d_in[5];
    const float* b1 = (const float*)d_in[6];
    const float* W2 = (const float*)d_in[7];
    const float* b2 = (const float*)d_in[8];
    float* out = (float*)d_out;

    void *pA1, *pHm, *pW1p, *pW2p;
    cudaGetSymbolAddress(&pA1, d_A1);
    cudaGetSymbolAddress(&pHm, d_Hm);
    cudaGetSymbolAddress(&pW1p, d_W1p);
    cudaGetSymbolAddress(&pW2p, d_W2p);

    const int SMEM0 = NSTAGE * (128 * SROW + 128 * SROW);   // 81920
    const int SMEM1 = NSTAGE * (64 * SROW + 128 * SROW);    // 61440
    cudaFuncSetAttribute(k_mma<0>, cudaFuncAttributeMaxDynamicSharedMemorySize, SMEM0);
    cudaFuncSetAttribute(k_mma<1>, cudaFuncAttributeMaxDynamicSharedMemorySize, SMEM1);

    k_init<<<(N_NODES + 255) / 256, 256>>>();
    k_probe<<<1, 256>>>(ei);
    k_bucket<<<(N_EDGES + 255) / 256, 256>>>(ei);
    {
        const int tot = HID * DIN + NODE_OUT * HID;
        k_prepW<<<(tot + 255) / 256, 256>>>(W1, W2);
    }
    k_buildH<<<MPAD, 64>>>(x, edge_attr);   // MPAD rows (incl. zero pad)

    // GEMM1: [MPAD,640] x [512,640]^T -> relu -> [hi,lo] fp16 Hm
    k_mma<0><<<dim3(HID / 128, MPAD / 128), 256, SMEM0>>>(
        (const unsigned short*)pA1, (const unsigned short*)pW1p, b1, pHm, K1E);
    // GEMM2: [MPAD,1024] x [128,1024]^T -> fp32 out   (64-row tiles: 782 CTAs)
    k_mma<1><<<dim3(NODE_OUT / 128, MPAD / 64), 256, SMEM1>>>(
        (const unsigned short*)pHm, (const unsigned short*)pW2p, b2, out, K2E);
}

// round 8
// speedup vs baseline: 3.8681x; 1.4848x over previous
#include <cuda_runtime.h>
#include <cuda_fp16.h>
#include <cstdint>

// ---------------------------------------------------------------------------
// Problem constants
// ---------------------------------------------------------------------------
#define N_NODES  50000
#define N_EDGES  800000
#define NODE_IN  128
#define EDGE_OUT 64
#define DIN      320
#define HID      512
#define NODE_OUT 128
#define CAP      96
#define MPAD     50048          // 391 * 128 (also divisible by 64)

// ---------------------------------------------------------------------------
// Static device scratch (__device__ globals only; no allocations)
// ---------------------------------------------------------------------------
__device__ int d_flag;
__device__ int d_cursor[N_NODES];
__device__ int d_bucket[N_NODES * CAP];
__device__ __align__(16) unsigned short d_A1[(size_t)MPAD * DIN];     // H  (fp16)
__device__ __align__(16) unsigned short d_Hm[(size_t)MPAD * HID];     // relu(HW1+b1) fp16
__device__ __align__(16) unsigned short d_W1p[HID * DIN];             // W1^T fp16
__device__ __align__(16) unsigned short d_W2p[NODE_OUT * HID];        // W2^T fp16

// ---------------------------------------------------------------------------
// Helpers
// ---------------------------------------------------------------------------
__device__ __forceinline__ uint32_t smem_u32_(const void* p) {
    uint32_t a;
    asm("{ .reg .u64 t; cvta.to.shared.u64 t, %1; cvt.u32.u64 %0, t; }" : "=r"(a) : "l"(p));
    return a;
}

__device__ __forceinline__ void cpa16(uint32_t s, const void* g) {
    asm volatile("cp.async.cg.shared.global [%0], [%1], 16;"
                 :: "r"(s), "l"(__cvta_generic_to_global(g)));
}
#define CP_COMMIT() asm volatile("cp.async.commit_group;")
#define CP_WAIT2()  asm volatile("cp.async.wait_group 2;")

#define LDSM4(r, a)                                                          \
    asm volatile("ldmatrix.sync.aligned.m8n8.x4.shared.b16 {%0,%1,%2,%3}, [%4];" \
        : "=r"((r)[0]), "=r"((r)[1]), "=r"((r)[2]), "=r"((r)[3]) : "r"(a))

__device__ __forceinline__ void mma16816(float* c, const uint32_t* a, const uint32_t* b) {
    asm volatile(
        "mma.sync.aligned.m16n8k16.row.col.f32.f16.f16.f32 "
        "{%0,%1,%2,%3}, {%4,%5,%6,%7}, {%8,%9}, {%0,%1,%2,%3};"
        : "+f"(c[0]), "+f"(c[1]), "+f"(c[2]), "+f"(c[3])
        : "r"(a[0]), "r"(a[1]), "r"(a[2]), "r"(a[3]), "r"(b[0]), "r"(b[1]));
}

// ---------------------------------------------------------------------------
// K0: init cursors + flag
// ---------------------------------------------------------------------------
__global__ void k_init() {
    int i = blockIdx.x * blockDim.x + threadIdx.x;
    if (i < N_NODES) d_cursor[i] = 0;
    if (i == 0) d_flag = 0;
}

// K1: dtype probe (int64 vs int32 edge_index)
__global__ void k_probe(const void* __restrict__ ei) {
    const long long v = ((const long long*)ei)[threadIdx.x];
    if (v < 0 || v >= (long long)N_NODES) d_flag = 1;
}

// K2: bucket edges by destination node
__global__ void k_bucket(const void* __restrict__ ei) {
    int e = blockIdx.x * blockDim.x + threadIdx.x;
    if (e >= N_EDGES) return;
    int c = d_flag ? ((const int*)ei)[N_EDGES + e]
                   : (int)((const long long*)ei)[N_EDGES + e];
    int pos = atomicAdd(&d_cursor[c], 1);
    if (pos < CAP) d_bucket[c * CAP + pos] = e;
}

// K2b: transpose weights + round to fp16
__global__ void k_prepW(const float* __restrict__ W1, const float* __restrict__ W2) {
    int i = blockIdx.x * blockDim.x + threadIdx.x;
    const int N1 = HID * DIN;
    if (i < N1) {
        int n = i / DIN, k = i % DIN;
        d_W1p[i] = __half_as_ushort(__float2half_rn(W1[(size_t)k * HID + n]));
    } else if (i < N1 + NODE_OUT * HID) {
        int j = i - N1;
        int n = j / HID, k = j % HID;
        d_W2p[j] = __half_as_ushort(__float2half_rn(W2[(size_t)k * NODE_OUT + n]));
    }
}

// ---------------------------------------------------------------------------
// K3: per-node reduce -> fp16 H row [x | sum | max | mean]
// Runs over MPAD rows; padding rows (n >= N_NODES) are zero-filled.
// ---------------------------------------------------------------------------
__global__ void __launch_bounds__(64) k_buildH(const float* __restrict__ x,
                                               const float* __restrict__ edge_attr) {
    __shared__ int se[CAP];
    __shared__ __align__(16) unsigned short rowbuf[DIN];
    const int n = blockIdx.x;
    const int f = threadIdx.x;

    if (n >= N_NODES) {            // zero padding rows for determinism
        uint4* g = (uint4*)(d_A1 + (size_t)n * DIN);
        uint4 z = make_uint4(0, 0, 0, 0);
        for (int w = f; w < DIN / 8; w += 64) g[w] = z;
        return;
    }

    const int total = d_cursor[n];
    const int ec = total < CAP ? total : CAP;
    for (int i = f; i < ec; i += 64) se[i] = d_bucket[n * CAP + i];
    __syncthreads();

    const float NEG_INF = __int_as_float(0xff800000u);
    float s0 = 0.f, s1 = 0.f, s2 = 0.f, s3 = 0.f;
    float m0 = NEG_INF, m1 = NEG_INF, m2 = NEG_INF, m3 = NEG_INF;

    int i = 0;
    for (; i + 4 <= ec; i += 4) {
        float v0 = __ldg(&edge_attr[(size_t)se[i + 0] * EDGE_OUT + f]);
        float v1 = __ldg(&edge_attr[(size_t)se[i + 1] * EDGE_OUT + f]);
        float v2 = __ldg(&edge_attr[(size_t)se[i + 2] * EDGE_OUT + f]);
        float v3 = __ldg(&edge_attr[(size_t)se[i + 3] * EDGE_OUT + f]);
        s0 += v0; s1 += v1; s2 += v2; s3 += v3;
        m0 = fmaxf(m0, v0); m1 = fmaxf(m1, v1);
        m2 = fmaxf(m2, v2); m3 = fmaxf(m3, v3);
    }
    for (; i < ec; i++) {
        float v = __ldg(&edge_attr[(size_t)se[i] * EDGE_OUT + f]);
        s0 += v; m0 = fmaxf(m0, v);
    }
    const float sum = (s0 + s1) + (s2 + s3);
    float mx = fmaxf(fmaxf(m0, m1), fmaxf(m2, m3));
    if (ec == 0) mx = 0.f;
    const float mean = sum / fmaxf((float)total, 1.f);

    float vals[5];
    vals[0] = x[(size_t)n * NODE_IN + f];
    vals[1] = x[(size_t)n * NODE_IN + 64 + f];
    vals[2] = sum; vals[3] = mx; vals[4] = mean;
#pragma unroll
    for (int c5 = 0; c5 < 5; c5++)
        rowbuf[c5 * 64 + f] = __half_as_ushort(__float2half_rn(vals[c5]));
    __syncthreads();

    uint4* g = (uint4*)(d_A1 + (size_t)n * DIN);
    const uint4* s4 = (const uint4*)rowbuf;
    for (int w = f; w < DIN / 8; w += 64) g[w] = s4[w];   // 40 uint4
}

// ---------------------------------------------------------------------------
// K4/K5: fp16 mma.sync GEMM with 4-stage cp.async ring.
// C = act(A @ B^T + bias).  BK=32, 8 warps.
// MODE 0: CTA 128x128 (2Mx4N warps), relu + fp16 -> d_Hm.
// MODE 1: CTA  64x128 (2Mx4N, 32-row warp tiles), fp32 + bias -> out.
// ---------------------------------------------------------------------------
#define SROW   80                // smem bytes per 32-half row (64B data + 16B pad)
#define NSTAGE 4

template <int MODE>
__global__ void __launch_bounds__(256, 2)
k_mma(const unsigned short* __restrict__ gA, const unsigned short* __restrict__ gB,
      const float* __restrict__ bias, void* __restrict__ outp, int Kp) {
    constexpr int MT   = (MODE == 0) ? 128 : 64;     // M tile
    constexpr int MFR  = (MODE == 0) ? 4 : 2;        // 16-row frags per warp
    constexpr int ATB  = MT * SROW;                  // A tile bytes
    constexpr int STB  = ATB + 128 * SROW;           // stage bytes (A + B)

    extern __shared__ __align__(16) char sm[];
    const int tid = threadIdx.x, L = tid & 31, wid = tid >> 5;
    const int wm = wid >> 2, wn = wid & 3;
    const int n0 = blockIdx.x * 128, row0 = blockIdx.y * MT;
    const uint32_t sb = smem_u32_(sm);

    float acc[MFR][4][4];
#pragma unroll
    for (int a = 0; a < MFR; a++)
#pragma unroll
        for (int b = 0; b < 4; b++)
#pragma unroll
            for (int c = 0; c < 4; c++) acc[a][b][c] = 0.f;

    const int r0c = tid >> 2, q0c = (tid & 3) * 16;                 // chunk 0
    const int r1c = (tid + 256) >> 2, q1c = ((tid + 256) & 3) * 16; // chunk 1

#define LOAD_STAGE(s, k0)                                                        \
    do {                                                                         \
        uint32_t Ab_ = sb + (s) * STB, Bb_ = Ab_ + ATB;                          \
        cpa16(Ab_ + r0c * SROW + q0c, gA + (size_t)(row0 + r0c) * Kp + (k0) + (q0c >> 1)); \
        if constexpr (MT == 128)                                                 \
            cpa16(Ab_ + r1c * SROW + q1c, gA + (size_t)(row0 + r1c) * Kp + (k0) + (q1c >> 1)); \
        cpa16(Bb_ + r0c * SROW + q0c, gB + (size_t)(n0 + r0c) * Kp + (k0) + (q0c >> 1));   \
        cpa16(Bb_ + r1c * SROW + q1c, gB + (size_t)(n0 + r1c) * Kp + (k0) + (q1c >> 1));   \
    } while (0)

    const int NT = Kp >> 5;
#pragma unroll
    for (int p = 0; p < 3; p++) {      // prologue: 3 stages in flight
        LOAD_STAGE(p, p << 5);
        CP_COMMIT();
    }

    for (int kt = 0; kt < NT; kt++) {
        CP_WAIT2();
        __syncthreads();

        if (kt + 3 < NT) LOAD_STAGE((kt + 3) & (NSTAGE - 1), (kt + 3) << 5);
        CP_COMMIT();

        const int s = kt & (NSTAGE - 1);
        const uint32_t Ab = sb + s * STB;
        const uint32_t Bb = Ab + ATB;
        const uint32_t aBase = Ab + (uint32_t)((wm * (MFR * 16) + (L & 15)) * SROW + ((L >> 4) << 4));
        const uint32_t bBase = Bb + (uint32_t)((wn * 32 + (L & 7) + ((L >> 4) << 3)) * SROW
                                               + (((L >> 3) & 1) << 4));
#pragma unroll
        for (int ks = 0; ks < 2; ks++) {
            uint32_t afr[MFR][4], bfr[2][4];
#pragma unroll
            for (int mf = 0; mf < MFR; mf++) LDSM4(afr[mf], aBase + mf * 16 * SROW + ks * 32);
#pragma unroll
            for (int nb = 0; nb < 2; nb++) LDSM4(bfr[nb], bBase + nb * 16 * SROW + ks * 32);
#pragma unroll
            for (int mf = 0; mf < MFR; mf++)
#pragma unroll
                for (int nf = 0; nf < 4; nf++)
                    mma16816(acc[mf][nf], afr[mf], &bfr[nf >> 1][(nf & 1) * 2]);
        }
    }
    __syncthreads();

    if (MODE == 0) {
        // relu + fp16 into d_Hm rows
        unsigned short* gO = (unsigned short*)outp;
        float* st = (float*)sm;
#pragma unroll 1
        for (int half = 0; half < 2; half++) {
            if (wm == half) {
#pragma unroll
                for (int mf = 0; mf < MFR; mf++)
#pragma unroll
                    for (int nf = 0; nf < 4; nf++) {
                        int r = mf * 16 + (L >> 2), c = wn * 32 + nf * 8 + (L & 3) * 2;
                        st[r * 128 + c]           = acc[mf][nf][0];
                        st[r * 128 + c + 1]       = acc[mf][nf][1];
                        st[(r + 8) * 128 + c]     = acc[mf][nf][2];
                        st[(r + 8) * 128 + c + 1] = acc[mf][nf][3];
                    }
            }
            __syncthreads();
            for (int idx = tid; idx < 64 * 16; idx += 256) {
                int r = idx >> 4, w = idx & 15;          // 16 uint4 per row
                uint4 pack;
                unsigned short* t8 = (unsigned short*)&pack;
#pragma unroll
                for (int q = 0; q < 8; q++) {
                    int t = w * 8 + q;
                    float v = st[r * 128 + t] + __ldg(bias + n0 + t);
                    v = fmaxf(v, 0.f);
                    t8[q] = __half_as_ushort(__float2half_rn(v));
                }
                size_t gr = (size_t)(row0 + half * 64 + r);
                *(uint4*)(gO + gr * HID + n0 + w * 8) = pack;
            }
            __syncthreads();
        }
    } else {
        // fp32 + bias, row-guarded
        float* gO = (float*)outp;
#pragma unroll
        for (int mf = 0; mf < MFR; mf++) {
            int r = row0 + wm * (MFR * 16) + mf * 16 + (L >> 2);
#pragma unroll
            for (int nf = 0; nf < 4; nf++) {
                int c = n0 + wn * 32 + nf * 8 + (L & 3) * 2;
                float b0 = __ldg(bias + c), b1 = __ldg(bias + c + 1);
                if (r < N_NODES) {
                    gO[(size_t)r * NODE_OUT + c]     = acc[mf][nf][0] + b0;
                    gO[(size_t)r * NODE_OUT + c + 1] = acc[mf][nf][1] + b1;
                }
                if (r + 8 < N_NODES) {
                    gO[(size_t)(r + 8) * NODE_OUT + c]     = acc[mf][nf][2] + b0;
                    gO[(size_t)(r + 8) * NODE_OUT + c + 1] = acc[mf][nf][3] + b1;
                }
            }
        }
    }
#undef LOAD_STAGE
}

// ---------------------------------------------------------------------------
// Host launcher (graph-capturable: kernel launches only)
// ---------------------------------------------------------------------------
extern "C" void kernel_launch(void* const* d_in, const int* in_sizes, int n_in,
                              void* d_out, int out_size) {
    const float* x         = (const float*)d_in[0];
    const void*  ei        = d_in[1];
    const float* edge_attr = (const float*)d_in[2];
    const float* W1 = (const float*)d_in[5];
    const float* b1 = (const float*)d_in[6];
    const float* W2 = (const float*)d_in[7];
    const float* b2 = (const float*)d_in[8];
    float* out = (float*)d_out;

    void *pA1, *pHm, *pW1p, *pW2p;
    cudaGetSymbolAddress(&pA1, d_A1);
    cudaGetSymbolAddress(&pHm, d_Hm);
    cudaGetSymbolAddress(&pW1p, d_W1p);
    cudaGetSymbolAddress(&pW2p, d_W2p);

    const int SMEM0 = NSTAGE * (128 * SROW + 128 * SROW);   // 81920
    const int SMEM1 = NSTAGE * (64 * SROW + 128 * SROW);    // 61440
    cudaFuncSetAttribute(k_mma<0>, cudaFuncAttributeMaxDynamicSharedMemorySize, SMEM0);
    cudaFuncSetAttribute(k_mma<1>, cudaFuncAttributeMaxDynamicSharedMemorySize, SMEM1);

    k_init<<<(N_NODES + 255) / 256, 256>>>();
    k_probe<<<1, 256>>>(ei);
    k_bucket<<<(N_EDGES + 255) / 256, 256>>>(ei);
    {
        const int tot = HID * DIN + NODE_OUT * HID;
        k_prepW<<<(tot + 255) / 256, 256>>>(W1, W2);
    }
    k_buildH<<<MPAD, 64>>>(x, edge_attr);   // MPAD rows (incl. zero pad)

    // GEMM1: [MPAD,320] x [512,320]^T -> relu -> fp16 Hm
    k_mma<0><<<dim3(HID / 128, MPAD / 128), 256, SMEM0>>>(
        (const unsigned short*)pA1, (const unsigned short*)pW1p, b1, pHm, DIN);
    // GEMM2: [MPAD,512] x [128,512]^T -> fp32 out   (64-row tiles: 782 CTAs)
    k_mma<1><<<dim3(NODE_OUT / 128, MPAD / 64), 256, SMEM1>>>(
        (const unsigned short*)pHm, (const unsigned short*)pW2p, b2, out, HID);
}